// round 5
// baseline (speedup 1.0000x reference)
#include <cuda_runtime.h>
#include <stdint.h>

#define BATCH   32
#define NBOX    8400
#define NCLS    80
#define NC      (NBOX*NCLS)       // 672000
#define TOPK    1024
#define CAP     2048
#define NBUCKET 4096
#define MAXDET  300
#define SCORE_T 0.001f
#define IOU_T   0.7f
#define SEGS    32
#define V4_PER_BATCH (NC/4)            // 168000
#define V4_PER_SEG   (V4_PER_BATCH/SEGS) // 5250

// ---------------- device scratch (static: no allocations allowed) ----------
__device__ unsigned int       g_hist[BATCH][NBUCKET];
__device__ int                g_pivot[BATCH];
__device__ int                g_candCount[BATCH];
__device__ unsigned long long g_candKeys[BATCH][CAP];
__device__ float              g_topScore[BATCH][TOPK];
__device__ float              g_candBox[BATCH][TOPK][4];
__device__ float              g_offY1[BATCH][TOPK];
__device__ float              g_offX1[BATCH][TOPK];
__device__ float              g_offY2[BATCH][TOPK];
__device__ float              g_offX2[BATCH][TOPK];
__device__ float              g_area[BATCH][TOPK];
__device__ int                g_cls[BATCH][TOPK];
__device__ unsigned int       g_mask[BATCH][TOPK][32];   // bit j of word w: i suppresses col w*32+j (already includes col>i)
__device__ unsigned int       g_rowAny[BATCH][32];

// ---------------- K0: zero per-run state ------------------------------------
__global__ void k_init() {
    int i = blockIdx.x * blockDim.x + threadIdx.x;
    if (i < BATCH * NBUCKET) (&g_hist[0][0])[i] = 0u;
    if (i < BATCH)           g_candCount[i] = 0;
    if (i < BATCH * 32)      (&g_rowAny[0][0])[i] = 0u;
}

// ---------------- K1: per-batch value histogram (4096 buckets) --------------
__global__ void k_hist(const float* __restrict__ scores) {
    int b = blockIdx.x, seg = blockIdx.y;
    __shared__ unsigned int sh[NBUCKET];
    for (int i = threadIdx.x; i < NBUCKET; i += blockDim.x) sh[i] = 0u;
    __syncthreads();
    const float4* p = (const float4*)(scores + (size_t)b * NC) + (size_t)seg * V4_PER_SEG;
    for (int i = threadIdx.x; i < V4_PER_SEG; i += blockDim.x) {
        float4 v = p[i];
        float a[4] = {v.x, v.y, v.z, v.w};
#pragma unroll
        for (int c = 0; c < 4; c++) {
            float s = a[c];
            if (s > SCORE_T) {
                int bk = (int)(s * 4096.0f); if (bk > NBUCKET - 1) bk = NBUCKET - 1;
                atomicAdd(&sh[bk], 1u);
            }
        }
    }
    __syncthreads();
    for (int i = threadIdx.x; i < NBUCKET; i += blockDim.x)
        if (sh[i]) atomicAdd(&g_hist[b][i], sh[i]);
}

// ---------------- K2: find pivot bucket so count(>=pivot) >= TOPK -----------
__global__ void k_pivot() {
    int b = blockIdx.x;
    __shared__ unsigned int chunk[256];
    unsigned int s = 0;
    int base = threadIdx.x * 16;
#pragma unroll
    for (int i = 0; i < 16; i++) s += g_hist[b][base + i];
    chunk[threadIdx.x] = s;
    __syncthreads();
    if (threadIdx.x == 0) {
        unsigned int acc = 0; int piv = 0; bool found = false;
        for (int c = 255; c >= 0 && !found; c--) {
            if (acc + chunk[c] >= TOPK) {
                unsigned int a2 = acc;
                for (int k2 = c * 16 + 15; k2 >= c * 16; k2--) {
                    a2 += g_hist[b][k2];
                    if (a2 >= TOPK) { piv = k2; found = true; break; }
                }
            } else acc += chunk[c];
        }
        g_pivot[b] = found ? piv : 0;
    }
}

// ---------------- K3: collect candidates >= pivot as 64-bit keys ------------
__global__ void k_collect(const float* __restrict__ scores) {
    int b = blockIdx.x, seg = blockIdx.y;
    int piv = g_pivot[b];
    const float4* p = (const float4*)(scores + (size_t)b * NC) + (size_t)seg * V4_PER_SEG;
    int flatBase = seg * V4_PER_SEG * 4;
    for (int i = threadIdx.x; i < V4_PER_SEG; i += blockDim.x) {
        float4 v = p[i];
        float a[4] = {v.x, v.y, v.z, v.w};
        int fb = flatBase + i * 4;
#pragma unroll
        for (int c = 0; c < 4; c++) {
            float s = a[c];
            if (s > SCORE_T) {
                int bk = (int)(s * 4096.0f); if (bk > NBUCKET - 1) bk = NBUCKET - 1;
                if (bk >= piv) {
                    int pos = atomicAdd(&g_candCount[b], 1);
                    if (pos < CAP) {
                        unsigned int sb = __float_as_uint(s);
                        g_candKeys[b][pos] =
                            ((unsigned long long)sb << 32) | (unsigned long long)(0xFFFFFFFFu - (unsigned)(fb + c));
                    }
                }
            }
        }
    }
}

// ---------------- K4: bitonic sort (descending) + gather/offset -------------
__global__ void k_sort(const float* __restrict__ boxes) {
    int b = blockIdx.x, tid = threadIdx.x;
    __shared__ unsigned long long sm[CAP];
    int cnt = g_candCount[b]; if (cnt > CAP) cnt = CAP;
    for (int i = tid; i < CAP; i += blockDim.x)
        sm[i] = (i < cnt) ? g_candKeys[b][i] : 0ull;
    __syncthreads();
    for (int k = 2; k <= CAP; k <<= 1)
        for (int j = k >> 1; j > 0; j >>= 1) {
            for (int i = tid; i < CAP; i += blockDim.x) {
                int p = i ^ j;
                if (p > i) {
                    unsigned long long A = sm[i], Bv = sm[p];
                    bool desc = ((i & k) == 0);
                    if (desc ? (A < Bv) : (A > Bv)) { sm[i] = Bv; sm[p] = A; }
                }
            }
            __syncthreads();
        }
    if (tid < TOPK) {
        unsigned long long key = sm[tid];
        float s = __uint_as_float((unsigned)(key >> 32));
        unsigned flat = 0xFFFFFFFFu - (unsigned)(key & 0xFFFFFFFFull);
        if (key == 0ull) { s = 0.0f; flat = 0u; }
        int bx = (int)(flat / NCLS), cl = (int)(flat % NCLS);
        const float* bp = boxes + ((size_t)b * NBOX + bx) * 4;
        float c0 = bp[0], c1 = bp[1], c2 = bp[2], c3 = bp[3];
        float off = (float)cl * 4096.0f;
        float o0 = c0 + off, o1 = c1 + off, o2 = c2 + off, o3 = c3 + off;
        // areas from OFFSET boxes, matching reference rounding: (x2-x1+1)*(y2-y1+1)
        float area = ((o3 - o1) + 1.0f) * ((o2 - o0) + 1.0f);
        g_topScore[b][tid] = s;
        g_candBox[b][tid][0] = c0; g_candBox[b][tid][1] = c1;
        g_candBox[b][tid][2] = c2; g_candBox[b][tid][3] = c3;
        g_offY1[b][tid] = o0; g_offX1[b][tid] = o1;
        g_offY2[b][tid] = o2; g_offX2[b][tid] = o3;
        g_area[b][tid] = area;
        g_cls[b][tid]  = cl;
    }
}

// ---------------- K5: suppression bitmask (64 rows per block) ---------------
__global__ void k_mask() {
    int b = blockIdx.x;
    int rbase = blockIdx.y * 64;
    __shared__ float sy1[TOPK], sx1[TOPK], sy2[TOPK], sx2[TOPK], sa[TOPK];
    for (int i = threadIdx.x; i < TOPK; i += blockDim.x) {
        sy1[i] = g_offY1[b][i]; sx1[i] = g_offX1[b][i];
        sy2[i] = g_offY2[b][i]; sx2[i] = g_offX2[b][i];
        sa[i]  = g_area[b][i];
    }
    __syncthreads();
    int w = threadIdx.x >> 5, lane = threadIdx.x & 31;
    for (int rr = 0; rr < 8; rr++) {
        int r = rbase + w * 8 + rr;
        float ry1 = sy1[r], rx1 = sx1[r], ry2 = sy2[r], rx2 = sx2[r], ra = sa[r];
        unsigned any = 0u;
        for (int cw = 0; cw < 32; cw++) {
            int col = cw * 32 + lane;
            float yy1 = fmaxf(ry1, sy1[col]);
            float xx1 = fmaxf(rx1, sx1[col]);
            float yy2 = fminf(ry2, sy2[col]);
            float xx2 = fminf(rx2, sx2[col]);
            float wd = fmaxf(0.0f, (xx2 - xx1) + 1.0f);
            float ht = fmaxf(0.0f, (yy2 - yy1) + 1.0f);
            float inter = wd * ht;
            float uni = (ra + sa[col]) - inter;
            bool bit = (inter > IOU_T * uni) && (col > r);
            unsigned m = __ballot_sync(0xffffffffu, bit);
            if (lane == 0) g_mask[b][r][cw] = m;
            any |= m;
        }
        if (lane == 0 && any) atomicOr(&g_rowAny[b][r >> 5], 1u << (r & 31));
    }
}

// ---------------- K6: serial greedy scan + stable partition + outputs -------
__global__ void k_final(float* __restrict__ out) {
    int b = blockIdx.x, t = threadIdx.x;
    int w = t >> 5, lane = t & 31;
    __shared__ unsigned int skeep[32];
    __shared__ unsigned int sra[32];
    __shared__ unsigned int warpTot[32];
    __shared__ unsigned int warpOff[32];
    __shared__ unsigned int sTotal;

    float myScore = g_topScore[b][t];
    bool k0 = myScore > SCORE_T;
    unsigned bal = __ballot_sync(0xffffffffu, k0);
    if (lane == 0) skeep[w] = bal;
    if (t < 32) sra[t] = g_rowAny[b][t];
    __syncthreads();

    if (w == 0) {
        unsigned kw  = skeep[lane];   // keep bits for items lane*32..+31
        unsigned raw = sra[lane];
        for (int g = 0; g < 32; g++) {
            unsigned curk  = __shfl_sync(0xffffffffu, kw, g);
            unsigned curra = __shfl_sync(0xffffffffu, raw, g);
            unsigned act = curk & curra;
            while (act) {
                int bit = __ffs(act) - 1;
                int i = g * 32 + bit;
                unsigned m = g_mask[b][i][lane];   // coalesced 128B row
                kw &= ~m;
                unsigned mg = __shfl_sync(0xffffffffu, m, g);
                curk &= ~mg;
                act &= ~((2u << bit) - 1u);        // clear bits <= bit (bit=31 -> 0)
                act &= curk;
            }
        }
        skeep[lane] = kw;
    }
    __syncthreads();

    unsigned kwword = skeep[w];
    bool keep = (kwword >> lane) & 1u;
    if (lane == 0) warpTot[w] = __popc(kwword);
    __syncthreads();
    if (t == 0) {
        unsigned acc = 0;
        for (int i = 0; i < 32; i++) { warpOff[i] = acc; acc += warpTot[i]; }
        sTotal = acc;
    }
    __syncthreads();

    unsigned keptBefore = warpOff[w] + __popc(kwword & ((1u << lane) - 1u));
    unsigned total = sTotal;
    unsigned pos = keep ? keptBefore : (total + ((unsigned)t - keptBefore));

    const int OFF_SCORES = BATCH * MAXDET * 4;
    const int OFF_LABELS = OFF_SCORES + BATCH * MAXDET;
    const int OFF_NVALID = OFF_LABELS + BATCH * MAXDET;

    if (pos < MAXDET) {
        float* ob = out + ((size_t)b * MAXDET + pos) * 4;
        ob[0] = g_candBox[b][t][0];
        ob[1] = g_candBox[b][t][1];
        ob[2] = g_candBox[b][t][2];
        ob[3] = g_candBox[b][t][3];
        out[OFF_SCORES + b * MAXDET + (int)pos] = keep ? myScore : 0.0f;
        out[OFF_LABELS + b * MAXDET + (int)pos] = (float)g_cls[b][t];
    }
    if (t == 0) {
        unsigned nv = total; if (nv > MAXDET) nv = MAXDET;
        out[OFF_NVALID + b] = (float)nv;
    }
}

// ---------------- launch -----------------------------------------------------
extern "C" void kernel_launch(void* const* d_in, const int* in_sizes, int n_in,
                              void* d_out, int out_size) {
    (void)n_in; (void)out_size;
    const float* boxes;
    const float* scores;
    if (in_sizes[0] == BATCH * NBOX * 4) {
        boxes  = (const float*)d_in[0];
        scores = (const float*)d_in[1];
    } else {
        boxes  = (const float*)d_in[1];
        scores = (const float*)d_in[0];
    }

    int initWords = BATCH * NBUCKET;  // dominant range
    k_init<<<(initWords + 255) / 256, 256>>>();

    dim3 gSeg(BATCH, SEGS);
    k_hist<<<gSeg, 256>>>(scores);
    k_pivot<<<BATCH, 256>>>();
    k_collect<<<gSeg, 256>>>(scores);
    k_sort<<<BATCH, 1024>>>(boxes);
    dim3 gMask(BATCH, TOPK / 64);
    k_mask<<<gMask, 256>>>();
    k_final<<<BATCH, 1024>>>((float*)d_out);
}

// round 6
// speedup vs baseline: 1.1592x; 1.1592x over previous
#include <cuda_runtime.h>
#include <stdint.h>

#define BATCH   32
#define NBOX    8400
#define NCLS    80
#define NC      (NBOX*NCLS)       // 672000
#define TOPK    1024
#define CAP     2048
#define CAP1    8192
#define MAXDET  300
#define SCORE_T 0.001f
#define IOU_T   0.7f
#define T0      0.995f
#define V4_PER_BATCH (NC/4)       // 168000
#define TOTAL_V4 (BATCH*V4_PER_BATCH)   // 5376000
#define SCAN_BLOCKS (TOTAL_V4/2048)     // 2625 (256 thr * 8 unroll)

// ---------------- device scratch (static) -----------------------------------
__device__ int                g_c1[BATCH];
__device__ unsigned long long g_cand1[BATCH][CAP1];
__device__ int                g_flag;
__device__ float              g_topScore[BATCH][TOPK];
__device__ float              g_candBox[BATCH][TOPK][4];
__device__ float              g_offY1[BATCH][TOPK];
__device__ float              g_offX1[BATCH][TOPK];
__device__ float              g_offY2[BATCH][TOPK];
__device__ float              g_offX2[BATCH][TOPK];
__device__ float              g_area[BATCH][TOPK];
__device__ int                g_cls[BATCH][TOPK];
__device__ unsigned int       g_mask[BATCH][TOPK][32];
__device__ unsigned int       g_rowAny[BATCH][32];

// ---------------- K0: zero per-run state ------------------------------------
__global__ void k_init() {
    int i = threadIdx.x;
    if (i < BATCH * 32) (&g_rowAny[0][0])[i] = 0u;
    if (i < BATCH)      g_c1[i] = 0;
    if (i == 0)         g_flag = 0;
}

// ---------------- K1: single bandwidth-bound pass, collect s > T0 -----------
__global__ void __launch_bounds__(256) k_scan(const float* __restrict__ scores) {
    int tid  = threadIdx.x;
    int lane = tid & 31;
    size_t blockBase = (size_t)blockIdx.x * 2048;   // float4 units
    const float4* __restrict__ p = (const float4*)scores;

    // 8 independent front-batched 128-bit loads (MLP_p1 = 8)
    float4 v[8];
#pragma unroll
    for (int k = 0; k < 8; k++)
        v[k] = p[blockBase + (size_t)k * 256 + tid];

    int b0 = (int)(blockBase / V4_PER_BATCH);
    int bL = (int)((blockBase + 2047) / V4_PER_BATCH);
    bool uniformB = (b0 == bL);

    // pass 1: count hits
    int cnt = 0;
#pragma unroll
    for (int k = 0; k < 8; k++) {
        float a[4] = {v[k].x, v[k].y, v[k].z, v[k].w};
#pragma unroll
        for (int c = 0; c < 4; c++) cnt += (a[c] > T0) ? 1 : 0;
    }

    if (uniformB) {
        // warp-aggregated reservation
        int incl = cnt;
#pragma unroll
        for (int o = 1; o < 32; o <<= 1) {
            int n = __shfl_up_sync(0xffffffffu, incl, o);
            if (lane >= o) incl += n;
        }
        int excl  = incl - cnt;
        int total = __shfl_sync(0xffffffffu, incl, 31);
        int base  = 0;
        if (total > 0) {
            if (lane == 0) base = atomicAdd(&g_c1[b0], total);
            base = __shfl_sync(0xffffffffu, base, 0);
        }
        if (cnt > 0) {
            int w = base + excl;
            size_t batchBase4 = (size_t)b0 * V4_PER_BATCH;
#pragma unroll
            for (int k = 0; k < 8; k++) {
                float a[4] = {v[k].x, v[k].y, v[k].z, v[k].w};
                size_t idx4 = blockBase + (size_t)k * 256 + tid;
#pragma unroll
                for (int c = 0; c < 4; c++) {
                    if (a[c] > T0) {
                        unsigned flat = (unsigned)((idx4 - batchBase4) * 4 + c);
                        unsigned sb = __float_as_uint(a[c]);
                        if (w < CAP1)
                            g_cand1[b0][w] = ((unsigned long long)sb << 32) |
                                             (unsigned long long)(0xFFFFFFFFu - flat);
                        w++;
                    }
                }
            }
        }
    } else {
        // rare boundary block: per-hit atomics
#pragma unroll
        for (int k = 0; k < 8; k++) {
            float a[4] = {v[k].x, v[k].y, v[k].z, v[k].w};
            size_t idx4 = blockBase + (size_t)k * 256 + tid;
            int be = (int)(idx4 / V4_PER_BATCH);
#pragma unroll
            for (int c = 0; c < 4; c++) {
                if (a[c] > T0) {
                    unsigned flat = (unsigned)((idx4 - (size_t)be * V4_PER_BATCH) * 4 + c);
                    unsigned sb = __float_as_uint(a[c]);
                    int pos = atomicAdd(&g_c1[be], 1);
                    if (pos < CAP1)
                        g_cand1[be][pos] = ((unsigned long long)sb << 32) |
                                           (unsigned long long)(0xFFFFFFFFu - flat);
                }
            }
        }
    }
}

// ---------------- K2: sanity check ------------------------------------------
__global__ void k_check() {
    int t = threadIdx.x;
    if (t < BATCH) {
        int c = g_c1[t];
        if (c < TOPK || c > CAP1) g_flag = 1;
    }
}

// ---------------- K3: guarded fallback (never taken for this data) ----------
__global__ void k_fallback(const float* __restrict__ scores) {
    if (g_flag == 0) return;
    int b = blockIdx.x, tid = threadIdx.x;
    __shared__ unsigned int sh[4096];
    __shared__ int sPiv;
    for (int i = tid; i < 4096; i += 256) sh[i] = 0u;
    __syncthreads();
    const float* sc = scores + (size_t)b * NC;
    for (int i = tid; i < NC; i += 256) {
        float s = sc[i];
        if (s > SCORE_T) {
            int bk = (int)(s * 4096.0f); if (bk > 4095) bk = 4095;
            atomicAdd(&sh[bk], 1u);
        }
    }
    __syncthreads();
    if (tid == 0) {
        unsigned acc = 0; int piv = 0;
        for (int k = 4095; k >= 0; k--) {
            acc += sh[k];
            if (acc >= TOPK) { piv = k; break; }
        }
        sPiv = piv;
        g_c1[b] = 0;
    }
    __syncthreads();
    int piv = sPiv;
    for (int i = tid; i < NC; i += 256) {
        float s = sc[i];
        if (s > SCORE_T) {
            int bk = (int)(s * 4096.0f); if (bk > 4095) bk = 4095;
            if (bk >= piv) {
                int pos = atomicAdd(&g_c1[b], 1);
                if (pos < CAP1) {
                    unsigned sb = __float_as_uint(s);
                    g_cand1[b][pos] = ((unsigned long long)sb << 32) |
                                      (unsigned long long)(0xFFFFFFFFu - (unsigned)i);
                }
            }
        }
    }
}

// ---------------- K4: refine -> exact top-1024 sort -> gather ---------------
__device__ __forceinline__ int fine_bucket(float s) {
    int bk = (int)((s - 0.9f) * 40960.0f);
    if (bk < 0) bk = 0; if (bk > 4095) bk = 4095;
    return bk;
}

__global__ void __launch_bounds__(1024) k_select(const float* __restrict__ boxes) {
    int b = blockIdx.x, tid = threadIdx.x;
    __shared__ unsigned int hist[4096];
    __shared__ unsigned long long sm[CAP];
    __shared__ unsigned int chunk[1024];
    __shared__ int sPiv;
    __shared__ int sCnt;

    int c = g_c1[b]; if (c > CAP1) c = CAP1;

    for (int i = tid; i < 4096; i += 1024) hist[i] = 0u;
    for (int i = tid; i < CAP;  i += 1024) sm[i] = 0ull;
    if (tid == 0) sCnt = 0;
    __syncthreads();

    for (int i = tid; i < c; i += 1024) {
        float s = __uint_as_float((unsigned)(g_cand1[b][i] >> 32));
        atomicAdd(&hist[fine_bucket(s)], 1u);
    }
    __syncthreads();

    unsigned ssum = 0;
#pragma unroll
    for (int j = 0; j < 4; j++) ssum += hist[tid * 4 + j];
    chunk[tid] = ssum;
    __syncthreads();

    if (tid == 0) {
        int target = c < TOPK ? c : TOPK;
        int piv = 0;
        if (target > 0) {
            unsigned acc = 0; bool found = false;
            for (int ch = 1023; ch >= 0 && !found; ch--) {
                if (acc + chunk[ch] >= (unsigned)target) {
                    unsigned a2 = acc;
                    for (int k2 = ch * 4 + 3; k2 >= ch * 4; k2--) {
                        a2 += hist[k2];
                        if (a2 >= (unsigned)target) { piv = k2; found = true; break; }
                    }
                } else acc += chunk[ch];
            }
        } else piv = 4096;
        sPiv = piv;
    }
    __syncthreads();

    int piv = sPiv;
    for (int i = tid; i < c; i += 1024) {
        unsigned long long key = g_cand1[b][i];
        float s = __uint_as_float((unsigned)(key >> 32));
        if (fine_bucket(s) >= piv) {
            int pos = atomicAdd(&sCnt, 1);
            if (pos < CAP) sm[pos] = key;
        }
    }
    __syncthreads();

    // bitonic sort, descending, CAP=2048
    for (int k = 2; k <= CAP; k <<= 1)
        for (int j = k >> 1; j > 0; j >>= 1) {
            for (int i = tid; i < CAP; i += 1024) {
                int p = i ^ j;
                if (p > i) {
                    unsigned long long A = sm[i], Bv = sm[p];
                    bool desc = ((i & k) == 0);
                    if (desc ? (A < Bv) : (A > Bv)) { sm[i] = Bv; sm[p] = A; }
                }
            }
            __syncthreads();
        }

    if (tid < TOPK) {
        unsigned long long key = sm[tid];
        float s = __uint_as_float((unsigned)(key >> 32));
        unsigned flat = 0xFFFFFFFFu - (unsigned)(key & 0xFFFFFFFFull);
        if (key == 0ull) { s = 0.0f; flat = 0u; }
        int bx = (int)(flat / NCLS), cl = (int)(flat % NCLS);
        const float* bp = boxes + ((size_t)b * NBOX + bx) * 4;
        float c0 = bp[0], c1 = bp[1], c2 = bp[2], c3 = bp[3];
        float off = (float)cl * 4096.0f;
        float o0 = c0 + off, o1 = c1 + off, o2 = c2 + off, o3 = c3 + off;
        float area = ((o3 - o1) + 1.0f) * ((o2 - o0) + 1.0f);
        g_topScore[b][tid] = s;
        g_candBox[b][tid][0] = c0; g_candBox[b][tid][1] = c1;
        g_candBox[b][tid][2] = c2; g_candBox[b][tid][3] = c3;
        g_offY1[b][tid] = o0; g_offX1[b][tid] = o1;
        g_offY2[b][tid] = o2; g_offX2[b][tid] = o3;
        g_area[b][tid] = area;
        g_cls[b][tid]  = cl;
    }
}

// ---------------- K5: suppression bitmask (64 rows per block) ---------------
__global__ void k_mask() {
    int b = blockIdx.x;
    int rbase = blockIdx.y * 64;
    __shared__ float sy1[TOPK], sx1[TOPK], sy2[TOPK], sx2[TOPK], sa[TOPK];
    for (int i = threadIdx.x; i < TOPK; i += blockDim.x) {
        sy1[i] = g_offY1[b][i]; sx1[i] = g_offX1[b][i];
        sy2[i] = g_offY2[b][i]; sx2[i] = g_offX2[b][i];
        sa[i]  = g_area[b][i];
    }
    __syncthreads();
    int w = threadIdx.x >> 5, lane = threadIdx.x & 31;
    for (int rr = 0; rr < 8; rr++) {
        int r = rbase + w * 8 + rr;
        float ry1 = sy1[r], rx1 = sx1[r], ry2 = sy2[r], rx2 = sx2[r], ra = sa[r];
        unsigned any = 0u;
        for (int cw = 0; cw < 32; cw++) {
            int col = cw * 32 + lane;
            float yy1 = fmaxf(ry1, sy1[col]);
            float xx1 = fmaxf(rx1, sx1[col]);
            float yy2 = fminf(ry2, sy2[col]);
            float xx2 = fminf(rx2, sx2[col]);
            float wd = fmaxf(0.0f, (xx2 - xx1) + 1.0f);
            float ht = fmaxf(0.0f, (yy2 - yy1) + 1.0f);
            float inter = wd * ht;
            float uni = (ra + sa[col]) - inter;
            bool bit = (inter > IOU_T * uni) && (col > r);
            unsigned m = __ballot_sync(0xffffffffu, bit);
            if (lane == 0) g_mask[b][r][cw] = m;
            any |= m;
        }
        if (lane == 0 && any) atomicOr(&g_rowAny[b][r >> 5], 1u << (r & 31));
    }
}

// ---------------- K6: serial greedy scan + stable partition + outputs -------
__global__ void k_final(float* __restrict__ out) {
    int b = blockIdx.x, t = threadIdx.x;
    int w = t >> 5, lane = t & 31;
    __shared__ unsigned int skeep[32];
    __shared__ unsigned int sra[32];
    __shared__ unsigned int warpTot[32];
    __shared__ unsigned int warpOff[32];
    __shared__ unsigned int sTotal;

    float myScore = g_topScore[b][t];
    bool k0 = myScore > SCORE_T;
    unsigned bal = __ballot_sync(0xffffffffu, k0);
    if (lane == 0) skeep[w] = bal;
    if (t < 32) sra[t] = g_rowAny[b][t];
    __syncthreads();

    if (w == 0) {
        unsigned kw  = skeep[lane];
        unsigned raw = sra[lane];
        for (int g = 0; g < 32; g++) {
            unsigned curk  = __shfl_sync(0xffffffffu, kw, g);
            unsigned curra = __shfl_sync(0xffffffffu, raw, g);
            unsigned act = curk & curra;
            while (act) {
                int bit = __ffs(act) - 1;
                int i = g * 32 + bit;
                unsigned m = g_mask[b][i][lane];
                kw &= ~m;
                unsigned mg = __shfl_sync(0xffffffffu, m, g);
                curk &= ~mg;
                act &= ~((2u << bit) - 1u);
                act &= curk;
            }
        }
        skeep[lane] = kw;
    }
    __syncthreads();

    unsigned kwword = skeep[w];
    bool keep = (kwword >> lane) & 1u;
    if (lane == 0) warpTot[w] = __popc(kwword);
    __syncthreads();
    if (t == 0) {
        unsigned acc = 0;
        for (int i = 0; i < 32; i++) { warpOff[i] = acc; acc += warpTot[i]; }
        sTotal = acc;
    }
    __syncthreads();

    unsigned keptBefore = warpOff[w] + __popc(kwword & ((1u << lane) - 1u));
    unsigned total = sTotal;
    unsigned pos = keep ? keptBefore : (total + ((unsigned)t - keptBefore));

    const int OFF_SCORES = BATCH * MAXDET * 4;
    const int OFF_LABELS = OFF_SCORES + BATCH * MAXDET;
    const int OFF_NVALID = OFF_LABELS + BATCH * MAXDET;

    if (pos < MAXDET) {
        float* ob = out + ((size_t)b * MAXDET + pos) * 4;
        ob[0] = g_candBox[b][t][0];
        ob[1] = g_candBox[b][t][1];
        ob[2] = g_candBox[b][t][2];
        ob[3] = g_candBox[b][t][3];
        out[OFF_SCORES + b * MAXDET + (int)pos] = keep ? myScore : 0.0f;
        out[OFF_LABELS + b * MAXDET + (int)pos] = (float)g_cls[b][t];
    }
    if (t == 0) {
        unsigned nv = total; if (nv > MAXDET) nv = MAXDET;
        out[OFF_NVALID + b] = (float)nv;
    }
}

// ---------------- launch -----------------------------------------------------
extern "C" void kernel_launch(void* const* d_in, const int* in_sizes, int n_in,
                              void* d_out, int out_size) {
    (void)n_in; (void)out_size;
    const float* boxes;
    const float* scores;
    if (in_sizes[0] == BATCH * NBOX * 4) {
        boxes  = (const float*)d_in[0];
        scores = (const float*)d_in[1];
    } else {
        boxes  = (const float*)d_in[1];
        scores = (const float*)d_in[0];
    }

    k_init<<<1, 1024>>>();
    k_scan<<<SCAN_BLOCKS, 256>>>(scores);
    k_check<<<1, 32>>>();
    k_fallback<<<BATCH, 256>>>(scores);
    k_select<<<BATCH, 1024>>>(boxes);
    dim3 gMask(BATCH, TOPK / 64);
    k_mask<<<gMask, 256>>>();
    k_final<<<BATCH, 1024>>>((float*)d_out);
}

// round 8
// speedup vs baseline: 1.4796x; 1.2764x over previous
#include <cuda_runtime.h>
#include <stdint.h>

#define BATCH   32
#define NBOX    8400
#define NCLS    80
#define NC      (NBOX*NCLS)       // 672000
#define TOPK    1024
#define CAP     2048
#define CAP1    8192
#define MAXDET  300
#define SCORE_T 0.001f
#define IOU_T   0.7f
#define T0      0.995f
#define V4_PER_BATCH (NC/4)             // 168000
#define TOTAL_V4 (BATCH*V4_PER_BATCH)   // 5376000
#define SCAN_BLOCKS (TOTAL_V4/2048)     // 2625 (256 thr * 8 unroll)

// ---------------- device scratch (static, zero-initialized at load) ---------
__device__ int                g_c1[BATCH];            // reset by k_select each run
__device__ unsigned long long g_cand1[BATCH][CAP1];
__device__ float              g_topScore[BATCH][TOPK];
__device__ float              g_candBox[BATCH][TOPK][4];
__device__ float              g_offY1[BATCH][TOPK];
__device__ float              g_offX1[BATCH][TOPK];
__device__ float              g_offY2[BATCH][TOPK];
__device__ float              g_offX2[BATCH][TOPK];
__device__ float              g_area[BATCH][TOPK];
__device__ int                g_cls[BATCH][TOPK];
__device__ unsigned int       g_mask[BATCH][TOPK][32];  // words cw >= r/32 valid; lower words never read
__device__ unsigned int       g_rowAny[BATCH][32];      // fully rewritten by k_mask each run

// ---------------- K1: single bandwidth pass, collect s > T0 -----------------
__global__ void __launch_bounds__(256) k_scan(const float* __restrict__ scores) {
    int tid  = threadIdx.x;
    int lane = tid & 31;
    size_t blockBase = (size_t)blockIdx.x * 2048;   // float4 units
    const float4* __restrict__ p = (const float4*)scores;

    float4 v[8];
#pragma unroll
    for (int k = 0; k < 8; k++)
        v[k] = p[blockBase + (size_t)k * 256 + tid];

    int b0 = (int)(blockBase / V4_PER_BATCH);
    int bL = (int)((blockBase + 2047) / V4_PER_BATCH);
    bool uniformB = (b0 == bL);

    int cnt = 0;
#pragma unroll
    for (int k = 0; k < 8; k++) {
        float a[4] = {v[k].x, v[k].y, v[k].z, v[k].w};
#pragma unroll
        for (int c = 0; c < 4; c++) cnt += (a[c] > T0) ? 1 : 0;
    }

    if (uniformB) {
        int incl = cnt;
#pragma unroll
        for (int o = 1; o < 32; o <<= 1) {
            int n = __shfl_up_sync(0xffffffffu, incl, o);
            if (lane >= o) incl += n;
        }
        int excl  = incl - cnt;
        int total = __shfl_sync(0xffffffffu, incl, 31);
        int base  = 0;
        if (total > 0) {
            if (lane == 0) base = atomicAdd(&g_c1[b0], total);
            base = __shfl_sync(0xffffffffu, base, 0);
        }
        if (cnt > 0) {
            int w = base + excl;
            size_t batchBase4 = (size_t)b0 * V4_PER_BATCH;
#pragma unroll
            for (int k = 0; k < 8; k++) {
                float a[4] = {v[k].x, v[k].y, v[k].z, v[k].w};
                size_t idx4 = blockBase + (size_t)k * 256 + tid;
#pragma unroll
                for (int c = 0; c < 4; c++) {
                    if (a[c] > T0) {
                        unsigned flat = (unsigned)((idx4 - batchBase4) * 4 + c);
                        unsigned sb = __float_as_uint(a[c]);
                        if (w < CAP1)
                            g_cand1[b0][w] = ((unsigned long long)sb << 32) |
                                             (unsigned long long)(0xFFFFFFFFu - flat);
                        w++;
                    }
                }
            }
        }
    } else {
#pragma unroll
        for (int k = 0; k < 8; k++) {
            float a[4] = {v[k].x, v[k].y, v[k].z, v[k].w};
            size_t idx4 = blockBase + (size_t)k * 256 + tid;
            int be = (int)(idx4 / V4_PER_BATCH);
#pragma unroll
            for (int c = 0; c < 4; c++) {
                if (a[c] > T0) {
                    unsigned flat = (unsigned)((idx4 - (size_t)be * V4_PER_BATCH) * 4 + c);
                    unsigned sb = __float_as_uint(a[c]);
                    int pos = atomicAdd(&g_c1[be], 1);
                    if (pos < CAP1)
                        g_cand1[be][pos] = ((unsigned long long)sb << 32) |
                                           (unsigned long long)(0xFFFFFFFFu - flat);
                }
            }
        }
    }
}

// ---------------- hybrid bitonic helpers ------------------------------------
__device__ __forceinline__ unsigned long long shfl_xor64(unsigned long long v, int lx) {
    return __shfl_xor_sync(0xffffffffu, v, lx);
}

// Thread t holds elements i0=2t (v0) and i1=2t+1 (v1). Runs stages j=jstart..1
// of bitonic phase k entirely in registers (valid for jstart<=32).
__device__ __forceinline__ void reg_phase(unsigned long long& v0, unsigned long long& v1,
                                          int t, int k, int jstart) {
    bool desc = ((t & (k >> 1)) == 0);   // (i & k)==0, bit0 of i never reaches k>=2
    for (int j = jstart; j >= 2; j >>= 1) {
        int lx = j >> 1;                 // lane xor <= 16 : within warp
        bool low = ((t & lx) == 0);
        bool takeMax = (low == desc);
        unsigned long long o0 = shfl_xor64(v0, lx);
        unsigned long long o1 = shfl_xor64(v1, lx);
        v0 = takeMax ? (v0 > o0 ? v0 : o0) : (v0 < o0 ? v0 : o0);
        v1 = takeMax ? (v1 > o1 ? v1 : o1) : (v1 < o1 ? v1 : o1);
    }
    // j == 1 : in-thread
    if (desc ? (v0 < v1) : (v0 > v1)) {
        unsigned long long tmp = v0; v0 = v1; v1 = tmp;
    }
}

// ---------------- K2: select (fallback + refine + sort + gather) ------------
__device__ __forceinline__ int fine_bucket(float s) {
    int bk = (int)((s - 0.9f) * 40960.0f);
    if (bk < 0) bk = 0; if (bk > 4095) bk = 4095;
    return bk;
}

__global__ void __launch_bounds__(1024) k_select(const float* __restrict__ boxes,
                                                 const float* __restrict__ scores) {
    int b = blockIdx.x, tid = threadIdx.x;
    __shared__ unsigned int hist[4096];
    __shared__ unsigned long long sm[CAP];
    __shared__ unsigned int chunk[1024];
    __shared__ int sPiv;
    __shared__ int sCnt;

    int c = g_c1[b]; if (c > CAP1) c = CAP1;

    // ---- guarded fallback (never taken for this distribution) ----
    if (g_c1[b] < TOPK || g_c1[b] > CAP1) {
        for (int i = tid; i < 4096; i += 1024) hist[i] = 0u;
        if (tid == 0) sCnt = 0;
        __syncthreads();
        const float* sc = scores + (size_t)b * NC;
        for (int i = tid; i < NC; i += 1024) {
            float s = sc[i];
            if (s > SCORE_T) {
                int bk = (int)(s * 4096.0f); if (bk > 4095) bk = 4095;
                atomicAdd(&hist[bk], 1u);
            }
        }
        __syncthreads();
        if (tid == 0) {
            unsigned acc = 0; int piv = 0;
            for (int k = 4095; k >= 0; k--) { acc += hist[k]; if (acc >= TOPK) { piv = k; break; } }
            sPiv = piv;
        }
        __syncthreads();
        int piv = sPiv;
        for (int i = tid; i < NC; i += 1024) {
            float s = sc[i];
            if (s > SCORE_T) {
                int bk = (int)(s * 4096.0f); if (bk > 4095) bk = 4095;
                if (bk >= piv) {
                    int pos = atomicAdd(&sCnt, 1);
                    if (pos < CAP1) {
                        unsigned sb = __float_as_uint(s);
                        g_cand1[b][pos] = ((unsigned long long)sb << 32) |
                                          (unsigned long long)(0xFFFFFFFFu - (unsigned)i);
                    }
                }
            }
        }
        __syncthreads();
        c = sCnt; if (c > CAP1) c = CAP1;
    }

    // ---- fine histogram -> pivot -> compact to <= CAP ----
    for (int i = tid; i < 4096; i += 1024) hist[i] = 0u;
    for (int i = tid; i < CAP;  i += 1024) sm[i] = 0ull;
    if (tid == 0) sCnt = 0;
    __syncthreads();

    for (int i = tid; i < c; i += 1024) {
        float s = __uint_as_float((unsigned)(g_cand1[b][i] >> 32));
        atomicAdd(&hist[fine_bucket(s)], 1u);
    }
    __syncthreads();

    unsigned ssum = 0;
#pragma unroll
    for (int j = 0; j < 4; j++) ssum += hist[tid * 4 + j];
    chunk[tid] = ssum;
    __syncthreads();

    if (tid == 0) {
        int target = c < TOPK ? c : TOPK;
        int piv = 4096;
        if (target > 0) {
            unsigned acc = 0; bool found = false;
            piv = 0;
            for (int ch = 1023; ch >= 0 && !found; ch--) {
                if (acc + chunk[ch] >= (unsigned)target) {
                    unsigned a2 = acc;
                    for (int k2 = ch * 4 + 3; k2 >= ch * 4; k2--) {
                        a2 += hist[k2];
                        if (a2 >= (unsigned)target) { piv = k2; found = true; break; }
                    }
                } else acc += chunk[ch];
            }
        }
        sPiv = piv;
    }
    __syncthreads();

    int piv = sPiv;
    for (int i = tid; i < c; i += 1024) {
        unsigned long long key = g_cand1[b][i];
        float s = __uint_as_float((unsigned)(key >> 32));
        if (fine_bucket(s) >= piv) {
            int pos = atomicAdd(&sCnt, 1);
            if (pos < CAP) sm[pos] = key;
        }
    }
    __syncthreads();

    // ---- hybrid bitonic sort, descending, CAP = 2048 ----
    {
        ulonglong2* sm2 = (ulonglong2*)sm;
        ulonglong2 vv = sm2[tid];
        unsigned long long v0 = vv.x, v1 = vv.y;
        // phases k = 2..64 fully in registers (all j <= 32)
        for (int k = 2; k <= 64; k <<= 1)
            reg_phase(v0, v1, tid, k, (k >> 1) > 32 ? 32 : (k >> 1));
        sm2[tid].x = v0; sm2[tid].y = v1;
        __syncthreads();
        // phases k = 128..2048: smem stages j >= 64, then register bundle j <= 32
        for (int k = 128; k <= CAP; k <<= 1) {
            for (int j = k >> 1; j >= 64; j >>= 1) {
                for (int i = tid; i < CAP; i += 1024) {
                    int p = i ^ j;
                    if (p > i) {
                        unsigned long long A = sm[i], Bv = sm[p];
                        bool desc = ((i & k) == 0);
                        if (desc ? (A < Bv) : (A > Bv)) { sm[i] = Bv; sm[p] = A; }
                    }
                }
                __syncthreads();
            }
            vv = sm2[tid]; v0 = vv.x; v1 = vv.y;
            reg_phase(v0, v1, tid, k, 32);
            sm2[tid].x = v0; sm2[tid].y = v1;
            __syncthreads();
        }
    }

    // ---- gather boxes / offsets for top-1024 ----
    if (tid < TOPK) {
        unsigned long long key = sm[tid];
        float s = __uint_as_float((unsigned)(key >> 32));
        unsigned flat = 0xFFFFFFFFu - (unsigned)(key & 0xFFFFFFFFull);
        if (key == 0ull) { s = 0.0f; flat = 0u; }
        int bx = (int)(flat / NCLS), cl = (int)(flat % NCLS);
        const float* bp = boxes + ((size_t)b * NBOX + bx) * 4;
        float c0 = bp[0], c1 = bp[1], c2 = bp[2], c3 = bp[3];
        float off = (float)cl * 4096.0f;
        float o0 = c0 + off, o1 = c1 + off, o2 = c2 + off, o3 = c3 + off;
        float area = ((o3 - o1) + 1.0f) * ((o2 - o0) + 1.0f);
        g_topScore[b][tid] = s;
        g_candBox[b][tid][0] = c0; g_candBox[b][tid][1] = c1;
        g_candBox[b][tid][2] = c2; g_candBox[b][tid][3] = c3;
        g_offY1[b][tid] = o0; g_offX1[b][tid] = o1;
        g_offY2[b][tid] = o2; g_offX2[b][tid] = o3;
        g_area[b][tid] = area;
        g_cls[b][tid]  = cl;
    }

    // reset counter for next graph replay (keeps launch sequence stateless)
    if (tid == 0) g_c1[b] = 0;
}

// ---------------- K3: triangular suppression bitmask ------------------------
__global__ void k_mask() {
    int b = blockIdx.x;
    int rbase = blockIdx.y * 64;
    __shared__ float sy1[TOPK], sx1[TOPK], sy2[TOPK], sx2[TOPK], sa[TOPK];
    __shared__ unsigned int sAny[2];
    if (threadIdx.x < 2) sAny[threadIdx.x] = 0u;
    for (int i = threadIdx.x; i < TOPK; i += blockDim.x) {
        sy1[i] = g_offY1[b][i]; sx1[i] = g_offX1[b][i];
        sy2[i] = g_offY2[b][i]; sx2[i] = g_offX2[b][i];
        sa[i]  = g_area[b][i];
    }
    __syncthreads();
    int w = threadIdx.x >> 5, lane = threadIdx.x & 31;
    for (int rr = 0; rr < 8; rr++) {
        int r = rbase + w * 8 + rr;
        float ry1 = sy1[r], rx1 = sx1[r], ry2 = sy2[r], rx2 = sx2[r], ra = sa[r];
        unsigned any = 0u;
        for (int cw = r >> 5; cw < 32; cw++) {       // triangular: only col words >= r/32
            int col = cw * 32 + lane;
            float yy1 = fmaxf(ry1, sy1[col]);
            float xx1 = fmaxf(rx1, sx1[col]);
            float yy2 = fminf(ry2, sy2[col]);
            float xx2 = fminf(rx2, sx2[col]);
            float wd = fmaxf(0.0f, (xx2 - xx1) + 1.0f);
            float ht = fmaxf(0.0f, (yy2 - yy1) + 1.0f);
            float inter = wd * ht;
            float uni = (ra + sa[col]) - inter;
            bool bit = (inter > IOU_T * uni) && (col > r);
            unsigned m = __ballot_sync(0xffffffffu, bit);
            if (lane == 0) g_mask[b][r][cw] = m;
            any |= m;
        }
        if (lane == 0 && any) atomicOr(&sAny[(r >> 5) - (rbase >> 5)], 1u << (r & 31));
    }
    __syncthreads();
    if (threadIdx.x < 2)
        g_rowAny[b][(rbase >> 5) + threadIdx.x] = sAny[threadIdx.x];  // full overwrite, no init kernel
}

// ---------------- K4: serial greedy scan + stable partition + outputs -------
__global__ void k_final(float* __restrict__ out) {
    int b = blockIdx.x, t = threadIdx.x;
    int w = t >> 5, lane = t & 31;
    __shared__ unsigned int skeep[32];
    __shared__ unsigned int sra[32];
    __shared__ unsigned int warpTot[32];
    __shared__ unsigned int warpOff[32];
    __shared__ unsigned int sTotal;

    float myScore = g_topScore[b][t];
    bool k0 = myScore > SCORE_T;
    unsigned bal = __ballot_sync(0xffffffffu, k0);
    if (lane == 0) skeep[w] = bal;
    if (t < 32) sra[t] = g_rowAny[b][t];
    __syncthreads();

    if (w == 0) {
        unsigned kw  = skeep[lane];
        unsigned raw = sra[lane];
        for (int g = 0; g < 32; g++) {
            unsigned curk  = __shfl_sync(0xffffffffu, kw, g);
            unsigned curra = __shfl_sync(0xffffffffu, raw, g);
            unsigned act = curk & curra;
            while (act) {
                int bit = __ffs(act) - 1;
                int i = g * 32 + bit;
                // words below i>>5 were never written (triangular) and are always zero
                unsigned m = (lane >= g) ? g_mask[b][i][lane] : 0u;
                kw &= ~m;
                unsigned mg = __shfl_sync(0xffffffffu, m, g);
                curk &= ~mg;
                act &= ~((2u << bit) - 1u);
                act &= curk;
            }
        }
        skeep[lane] = kw;
    }
    __syncthreads();

    unsigned kwword = skeep[w];
    bool keep = (kwword >> lane) & 1u;
    if (lane == 0) warpTot[w] = __popc(kwword);
    __syncthreads();
    if (t == 0) {
        unsigned acc = 0;
        for (int i = 0; i < 32; i++) { warpOff[i] = acc; acc += warpTot[i]; }
        sTotal = acc;
    }
    __syncthreads();

    unsigned keptBefore = warpOff[w] + __popc(kwword & ((1u << lane) - 1u));
    unsigned total = sTotal;
    unsigned pos = keep ? keptBefore : (total + ((unsigned)t - keptBefore));

    const int OFF_SCORES = BATCH * MAXDET * 4;
    const int OFF_LABELS = OFF_SCORES + BATCH * MAXDET;
    const int OFF_NVALID = OFF_LABELS + BATCH * MAXDET;

    if (pos < MAXDET) {
        float* ob = out + ((size_t)b * MAXDET + pos) * 4;
        ob[0] = g_candBox[b][t][0];
        ob[1] = g_candBox[b][t][1];
        ob[2] = g_candBox[b][t][2];
        ob[3] = g_candBox[b][t][3];
        out[OFF_SCORES + b * MAXDET + (int)pos] = keep ? myScore : 0.0f;
        out[OFF_LABELS + b * MAXDET + (int)pos] = (float)g_cls[b][t];
    }
    if (t == 0) {
        unsigned nv = total; if (nv > MAXDET) nv = MAXDET;
        out[OFF_NVALID + b] = (float)nv;
    }
}

// ---------------- launch -----------------------------------------------------
extern "C" void kernel_launch(void* const* d_in, const int* in_sizes, int n_in,
                              void* d_out, int out_size) {
    (void)n_in; (void)out_size;
    const float* boxes;
    const float* scores;
    if (in_sizes[0] == BATCH * NBOX * 4) {
        boxes  = (const float*)d_in[0];
        scores = (const float*)d_in[1];
    } else {
        boxes  = (const float*)d_in[1];
        scores = (const float*)d_in[0];
    }

    k_scan<<<SCAN_BLOCKS, 256>>>(scores);
    k_select<<<BATCH, 1024>>>(boxes, scores);
    dim3 gMask(BATCH, TOPK / 64);
    k_mask<<<gMask, 256>>>();
    k_final<<<BATCH, 1024>>>((float*)d_out);
}